// round 16
// baseline (speedup 1.0000x reference)
#include <cuda_runtime.h>

#define NLL_EPS 1e-9f
#define NLL_LOGEPSINV 20.7232658f   // -ln(1e-9)
#define NLL_LN2 0.69314718056f
#define NLL_BLOCKS 888              // 148 SMs x 6 CTAs -> one wave at ~40 regs
#define NLL_THREADS 256

// ---------------- device-global scratch (static, no allocations) ----------------
__device__ double g_partL[NLL_BLOCKS];
__device__ double g_partS[NLL_BLOCKS];
__device__ unsigned int g_ticket = 0;

// Accurate fp32 exp — FROZEN, used by the d=31-censored slow path only.
__device__ __forceinline__ float nll_expf(float x)
{
    const float LOG2E   = 1.4426950408889634f;
    const float LN2_HI  = 0.693359375f;
    const float LN2_LO  = -2.12194440e-4f;
    float t = fmaf(x, LOG2E, 12582912.0f);     // round-to-nearest via magic
    float k = t - 12582912.0f;
    float r = fmaf(-k, LN2_HI, x);
    r       = fmaf(-k, LN2_LO, r);
    float p = 1.9841270e-4f;
    p = fmaf(p, r, 1.3888889e-3f);
    p = fmaf(p, r, 8.3333333e-3f);
    p = fmaf(p, r, 4.1666667e-2f);
    p = fmaf(p, r, 1.6666667e-1f);
    p = fmaf(p, r, 0.5f);
    p = fmaf(p, r, 1.0f);
    p = fmaf(p, r, 1.0f);
    int ik = (int)k;
    return p * __int_as_float((ik + 127) << 23);
}

// ---------------- single fused kernel -----------------------------------------
// 4 lanes per row, 8 rows per warp. Lane l: q=l&3 owns cols [8q, 8q+8).
__global__ __launch_bounds__(NLL_THREADS, 6)
void nll_kernel(const float* __restrict__ preds,
                const int2*  __restrict__ targets,
                const float* __restrict__ weight,
                const float* __restrict__ sw,
                float*       __restrict__ out,
                int nrows)
{
    const unsigned FULL = 0xffffffffu;

    // ---- per-block w_cummean (warp 0 scan into smem) ----
    __shared__ float s_wcm[32];
    __shared__ float s_w[32];
    if (threadIdx.x < 32) {
        float w = weight[threadIdx.x];
        s_w[threadIdx.x] = w;
        float v = w;
        #pragma unroll
        for (int o = 1; o < 32; o <<= 1) {
            float u = __shfl_up_sync(FULL, v, o);
            if ((threadIdx.x & 31) >= o) v += u;
        }
        s_wcm[threadIdx.x] = v / (float)(threadIdx.x + 1);
    }
    __syncthreads();

    const int tid   = blockIdx.x * blockDim.x + threadIdx.x;
    const int lane  = threadIdx.x & 31;
    const int q     = lane & 3;
    const int grp   = lane >> 2;
    const int gwarp = tid >> 5;
    const int nWarps = (gridDim.x * blockDim.x) >> 5;
    const int stride = nWarps * 8;          // rows consumed chip-wide per iter

    // hoisted strided pointers
    int row = gwarp * 8 + grp;
    const float4* pP = reinterpret_cast<const float4*>(preds + (size_t)row * 32 + q * 8);
    const int2*   pT = targets + row;
    const float*  pS = sw + row;
    const long    stepP = (long)stride * 8;   // float4 units
    const long    stepT = (long)stride;

    float accL = 0.0f;
    float accS = 0.0f;

    for (; row < nrows; row += stride, pP += stepP, pT += stepT, pS += stepT) {
        // ---- issue all independent loads up front ----
        float4 a = pP[0];
        float4 b = pP[1];
        int2 tg = pT[0];
        float swv = (q == 0) ? pS[0] : 0.0f;

        // ---- zero-register L2 prefetch, DISTANCE 2 iterations ahead ----
        // (covers DRAM->L2 fill latency behind ~2 iterations of math across
        //  12 warps/SMSP; prefetch to out-of-range addresses is ignored.)
        asm volatile("prefetch.global.L2 [%0];" :: "l"(pP + 2 * stepP));
        asm volatile("prefetch.global.L2 [%0];" :: "l"(pT + 2 * stepT));

        const int  d  = min(max(tg.x, 0), 31);
        const bool ev = (tg.y != 0);
        const int  qd = d >> 3;
        const int  jd = d & 7;

        // d==31 censored rows need reference-matching crumbs -> slow path
        const bool slow = __any_sync(FULL, !ev && (d == 31));

        float l;  // per-row loss -log(x), meaningful on q==0 lanes
        if (!slow) {
            // ---- FAST: __expf on raw preds (shift-invariant softmax) ----
            float e0 = __expf(a.x), e1 = __expf(a.y);
            float e2 = __expf(a.z), e3 = __expf(a.w);
            float e4 = __expf(b.x), e5 = __expf(b.y);
            float e6 = __expf(b.z), e7 = __expf(b.w);

            // running prefix within chunk; r7 doubles as the chunk sum
            float r0 = e0;
            float r1 = r0 + e1;
            float r2 = r1 + e2;
            float r3 = r2 + e3;
            float r4 = r3 + e4;
            float r5 = r4 + e5;
            float r6 = r5 + e6;
            float r7 = r6 + e7;

            // row sum from chunk sums (2-stage butterfly)
            float s = r7;
            s += __shfl_xor_sync(FULL, s, 1);
            s += __shfl_xor_sync(FULL, s, 2);

            // w = ev ? e[jd] : r[jd]  (SEL tree on jd bits)
            float w0 = ev ? e0 : r0, w1 = ev ? e1 : r1;
            float w2 = ev ? e2 : r2, w3 = ev ? e3 : r3;
            float w4 = ev ? e4 : r4, w5 = ev ? e5 : r5;
            float w6 = ev ? e6 : r6, w7 = ev ? e7 : r7;
            float t01 = (jd & 1) ? w1 : w0;
            float t23 = (jd & 1) ? w3 : w2;
            float t45 = (jd & 1) ? w5 : w4;
            float t67 = (jd & 1) ? w7 : w6;
            float t03 = (jd & 2) ? t23 : t01;
            float t47 = (jd & 2) ? t67 : t45;
            float wsel = (jd & 4) ? t47 : t03;

            // numerator: event -> e_d ; censored -> sum_{j<=d} e_j
            float val = (q < qd) ? (ev ? 0.0f : r7)
                                 : ((q == qd) ? wsel : 0.0f);
            val += __shfl_xor_sync(FULL, val, 1);
            val += __shfl_xor_sync(FULL, val, 2);

            // log-domain loss (lg2), no division
            float y = ev ? val : fmaxf(s - val, NLL_EPS * s);
            float lg = (__log2f(s) - __log2f(y)) * NLL_LN2;
            l = fminf(fmaxf(lg, 0.0f), NLL_LOGEPSINV);
        } else {
            // ---- SLOW: frozen numerics (matches reference crumbs for d=31) ----
            float m = fmaxf(fmaxf(fmaxf(a.x, a.y), fmaxf(a.z, a.w)),
                            fmaxf(fmaxf(b.x, b.y), fmaxf(b.z, b.w)));
            m = fmaxf(m, __shfl_xor_sync(FULL, m, 1));
            m = fmaxf(m, __shfl_xor_sync(FULL, m, 2));

            float e0 = nll_expf(a.x - m), e1 = nll_expf(a.y - m);
            float e2 = nll_expf(a.z - m), e3 = nll_expf(a.w - m);
            float e4 = nll_expf(b.x - m), e5 = nll_expf(b.y - m);
            float e6 = nll_expf(b.z - m), e7 = nll_expf(b.w - m);
            float s = ((e0 + e1) + (e2 + e3)) + ((e4 + e5) + (e6 + e7));
            s += __shfl_xor_sync(FULL, s, 1);
            s += __shfl_xor_sync(FULL, s, 2);

            float c = 0.f, part = 0.f, sel = 0.f;
            {
                float pj;
                #define NLL_QSTEP(VAL, J)                \
                    pj = __fdiv_rn((VAL), s);            \
                    c += pj;                             \
                    if ((J) <= jd) part += pj;           \
                    if ((J) == jd) sel = pj;
                NLL_QSTEP(e0, 0) NLL_QSTEP(e1, 1) NLL_QSTEP(e2, 2) NLL_QSTEP(e3, 3)
                NLL_QSTEP(e4, 4) NLL_QSTEP(e5, 5) NLL_QSTEP(e6, 6) NLL_QSTEP(e7, 7)
                #undef NLL_QSTEP
            }
            float c0 = __shfl_sync(FULL, c, 0, 4);
            float c1 = __shfl_sync(FULL, c, 1, 4);
            float c2 = __shfl_sync(FULL, c, 2, 4);
            float ex = 0.f;
            if (q >= 1) ex = c0;
            if (q >= 2) ex += c1;
            if (q >= 3) ex += c2;
            float numc = ev ? sel : (ex + part);
            float num  = __shfl_sync(FULL, numc, qd, 4);

            float xq = ev ? num : fminf(fmaxf(1.0f - num, NLL_EPS), 1.0f);
            l = -__logf(xq);
        }

        // ---- loss accumulation (q==0 lanes only) ----
        if (q == 0) {
            float wv = ev ? s_w[d] : s_wcm[d];
            accL = fmaf(l * wv, swv, accL);
            accS += swv;
        }
    }

    // ---- warp reduce ----
    #pragma unroll
    for (int o = 16; o > 0; o >>= 1) {
        accL += __shfl_xor_sync(FULL, accL, o);
        accS += __shfl_xor_sync(FULL, accS, o);
    }

    __shared__ float sL[8], sS[8];
    const int wib = threadIdx.x >> 5;
    if (lane == 0) { sL[wib] = accL; sS[wib] = accS; }
    __syncthreads();
    if (threadIdx.x == 0) {
        float bl = 0.f, bs = 0.f;
        #pragma unroll
        for (int i = 0; i < 8; ++i) { bl += sL[i]; bs += sS[i]; }
        g_partL[blockIdx.x] = (double)bl;
        g_partS[blockIdx.x] = (double)bs;
    }

    // ---- last-block finalize ----
    __shared__ bool s_last;
    __threadfence();
    if (threadIdx.x == 0) {
        unsigned t = atomicAdd(&g_ticket, 1u);
        s_last = (t == gridDim.x - 1);
    }
    __syncthreads();
    if (s_last) {
        __threadfence();
        double l2 = 0.0, w2 = 0.0;
        for (int i = threadIdx.x; i < (int)gridDim.x; i += blockDim.x) {
            l2 += g_partL[i];
            w2 += g_partS[i];
        }
        #pragma unroll
        for (int o = 16; o > 0; o >>= 1) {
            l2 += __shfl_xor_sync(FULL, l2, o);
            w2 += __shfl_xor_sync(FULL, w2, o);
        }
        __shared__ double dL[8], dS[8];
        if (lane == 0) { dL[wib] = l2; dS[wib] = w2; }
        __syncthreads();
        if (threadIdx.x == 0) {
            double tl = 0.0, tw = 0.0;
            #pragma unroll
            for (int i = 0; i < 8; ++i) { tl += dL[i]; tw += dS[i]; }
            double denom = tw > (double)NLL_EPS ? tw : (double)NLL_EPS;
            out[0] = (float)(tl / denom);
            g_ticket = 0;   // reset for next graph replay
        }
    }
}

// ---------------- launch --------------------------------------------------------
extern "C" void kernel_launch(void* const* d_in, const int* in_sizes, int n_in,
                              void* d_out, int out_size)
{
    const float* preds   = (const float*)d_in[0];
    const int2*  targets = (const int2*)d_in[1];
    const float* weight  = (const float*)d_in[2];
    const float* sw      = (const float*)d_in[3];
    float* out = (float*)d_out;

    int nrows = in_sizes[0] / 32;

    nll_kernel<<<NLL_BLOCKS, NLL_THREADS>>>(preds, targets, weight, sw, out, nrows);
}

// round 17
// speedup vs baseline: 1.1075x; 1.1075x over previous
#include <cuda_runtime.h>

#define NLL_EPS 1e-9f
#define NLL_LOGEPSINV 20.7232658f   // -ln(1e-9)
#define NLL_LN2 0.69314718056f
#define NLL_BLOCKS 888              // 148 SMs x 6 CTAs -> one wave at ~40 regs
#define NLL_THREADS 256

// ---------------- device-global scratch (static, no allocations) ----------------
__device__ double g_partL[NLL_BLOCKS];
__device__ double g_partS[NLL_BLOCKS];
__device__ unsigned int g_ticket = 0;

// Accurate fp32 exp — FROZEN, used by the d=31-censored slow path only.
__device__ __forceinline__ float nll_expf(float x)
{
    const float LOG2E   = 1.4426950408889634f;
    const float LN2_HI  = 0.693359375f;
    const float LN2_LO  = -2.12194440e-4f;
    float t = fmaf(x, LOG2E, 12582912.0f);     // round-to-nearest via magic
    float k = t - 12582912.0f;
    float r = fmaf(-k, LN2_HI, x);
    r       = fmaf(-k, LN2_LO, r);
    float p = 1.9841270e-4f;
    p = fmaf(p, r, 1.3888889e-3f);
    p = fmaf(p, r, 8.3333333e-3f);
    p = fmaf(p, r, 4.1666667e-2f);
    p = fmaf(p, r, 1.6666667e-1f);
    p = fmaf(p, r, 0.5f);
    p = fmaf(p, r, 1.0f);
    p = fmaf(p, r, 1.0f);
    int ik = (int)k;
    return p * __int_as_float((ik + 127) << 23);
}

// ---------------- single fused kernel -----------------------------------------
// 4 lanes per row, 8 rows per warp. Lane l: q=l&3 owns cols [8q, 8q+8).
__global__ __launch_bounds__(NLL_THREADS, 6)
void nll_kernel(const float* __restrict__ preds,
                const int2*  __restrict__ targets,
                const float* __restrict__ weight,
                const float* __restrict__ sw,
                float*       __restrict__ out,
                int nrows)
{
    const unsigned FULL = 0xffffffffu;

    // ---- per-block w_cummean (warp 0 scan into smem) ----
    __shared__ float s_wcm[32];
    __shared__ float s_w[32];
    if (threadIdx.x < 32) {
        float w = weight[threadIdx.x];
        s_w[threadIdx.x] = w;
        float v = w;
        #pragma unroll
        for (int o = 1; o < 32; o <<= 1) {
            float u = __shfl_up_sync(FULL, v, o);
            if ((threadIdx.x & 31) >= o) v += u;
        }
        s_wcm[threadIdx.x] = v / (float)(threadIdx.x + 1);
    }
    __syncthreads();

    const int tid   = blockIdx.x * blockDim.x + threadIdx.x;
    const int lane  = threadIdx.x & 31;
    const int q     = lane & 3;
    const int grp   = lane >> 2;
    const int gwarp = tid >> 5;
    const int nWarps = (gridDim.x * blockDim.x) >> 5;
    const int stride = nWarps * 8;          // rows consumed chip-wide per iter

    // hoisted strided pointers
    int row = gwarp * 8 + grp;
    const float4* pP = reinterpret_cast<const float4*>(preds + (size_t)row * 32 + q * 8);
    const int2*   pT = targets + row;
    const float*  pS = sw + row;
    const long    stepP = (long)stride * 8;   // float4 units
    const long    stepT = (long)stride;

    float accL = 0.0f;
    float accS = 0.0f;

    for (; row < nrows; row += stride, pP += stepP, pT += stepT, pS += stepT) {
        // ---- issue all independent loads up front ----
        float4 a = pP[0];
        float4 b = pP[1];
        int2 tg = pT[0];
        float swv = (q == 0) ? pS[0] : 0.0f;

        // ---- zero-register L2 prefetch of NEXT iteration's preds line ----
        // (address equals the next loop pointer value -> no extra ALU math;
        //  lane's 32B chunk lives in the 128B row line, so one prefetch covers
        //  both float4 loads; prefetch to an out-of-range address is ignored.)
        asm volatile("prefetch.global.L2 [%0];" :: "l"(pP + stepP));

        const int  d  = min(max(tg.x, 0), 31);
        const bool ev = (tg.y != 0);
        const int  qd = d >> 3;
        const int  jd = d & 7;

        // d==31 censored rows need reference-matching crumbs -> slow path
        const bool slow = __any_sync(FULL, !ev && (d == 31));

        float l;  // per-row loss -log(x), meaningful on q==0 lanes
        if (!slow) {
            // ---- FAST: __expf on raw preds (shift-invariant softmax) ----
            float e0 = __expf(a.x), e1 = __expf(a.y);
            float e2 = __expf(a.z), e3 = __expf(a.w);
            float e4 = __expf(b.x), e5 = __expf(b.y);
            float e6 = __expf(b.z), e7 = __expf(b.w);

            // running prefix within chunk; r7 doubles as the chunk sum
            float r0 = e0;
            float r1 = r0 + e1;
            float r2 = r1 + e2;
            float r3 = r2 + e3;
            float r4 = r3 + e4;
            float r5 = r4 + e5;
            float r6 = r5 + e6;
            float r7 = r6 + e7;

            // row sum from chunk sums (2-stage butterfly)
            float s = r7;
            s += __shfl_xor_sync(FULL, s, 1);
            s += __shfl_xor_sync(FULL, s, 2);

            // w = ev ? e[jd] : r[jd]  (SEL tree on jd bits)
            float w0 = ev ? e0 : r0, w1 = ev ? e1 : r1;
            float w2 = ev ? e2 : r2, w3 = ev ? e3 : r3;
            float w4 = ev ? e4 : r4, w5 = ev ? e5 : r5;
            float w6 = ev ? e6 : r6, w7 = ev ? e7 : r7;
            float t01 = (jd & 1) ? w1 : w0;
            float t23 = (jd & 1) ? w3 : w2;
            float t45 = (jd & 1) ? w5 : w4;
            float t67 = (jd & 1) ? w7 : w6;
            float t03 = (jd & 2) ? t23 : t01;
            float t47 = (jd & 2) ? t67 : t45;
            float wsel = (jd & 4) ? t47 : t03;

            // numerator: event -> e_d ; censored -> sum_{j<=d} e_j
            float val = (q < qd) ? (ev ? 0.0f : r7)
                                 : ((q == qd) ? wsel : 0.0f);
            val += __shfl_xor_sync(FULL, val, 1);
            val += __shfl_xor_sync(FULL, val, 2);

            // log-domain loss (lg2), no division
            float y = ev ? val : fmaxf(s - val, NLL_EPS * s);
            float lg = (__log2f(s) - __log2f(y)) * NLL_LN2;
            l = fminf(fmaxf(lg, 0.0f), NLL_LOGEPSINV);
        } else {
            // ---- SLOW: frozen numerics (matches reference crumbs for d=31) ----
            float m = fmaxf(fmaxf(fmaxf(a.x, a.y), fmaxf(a.z, a.w)),
                            fmaxf(fmaxf(b.x, b.y), fmaxf(b.z, b.w)));
            m = fmaxf(m, __shfl_xor_sync(FULL, m, 1));
            m = fmaxf(m, __shfl_xor_sync(FULL, m, 2));

            float e0 = nll_expf(a.x - m), e1 = nll_expf(a.y - m);
            float e2 = nll_expf(a.z - m), e3 = nll_expf(a.w - m);
            float e4 = nll_expf(b.x - m), e5 = nll_expf(b.y - m);
            float e6 = nll_expf(b.z - m), e7 = nll_expf(b.w - m);
            float s = ((e0 + e1) + (e2 + e3)) + ((e4 + e5) + (e6 + e7));
            s += __shfl_xor_sync(FULL, s, 1);
            s += __shfl_xor_sync(FULL, s, 2);

            float c = 0.f, part = 0.f, sel = 0.f;
            {
                float pj;
                #define NLL_QSTEP(VAL, J)                \
                    pj = __fdiv_rn((VAL), s);            \
                    c += pj;                             \
                    if ((J) <= jd) part += pj;           \
                    if ((J) == jd) sel = pj;
                NLL_QSTEP(e0, 0) NLL_QSTEP(e1, 1) NLL_QSTEP(e2, 2) NLL_QSTEP(e3, 3)
                NLL_QSTEP(e4, 4) NLL_QSTEP(e5, 5) NLL_QSTEP(e6, 6) NLL_QSTEP(e7, 7)
                #undef NLL_QSTEP
            }
            float c0 = __shfl_sync(FULL, c, 0, 4);
            float c1 = __shfl_sync(FULL, c, 1, 4);
            float c2 = __shfl_sync(FULL, c, 2, 4);
            float ex = 0.f;
            if (q >= 1) ex = c0;
            if (q >= 2) ex += c1;
            if (q >= 3) ex += c2;
            float numc = ev ? sel : (ex + part);
            float num  = __shfl_sync(FULL, numc, qd, 4);

            float xq = ev ? num : fminf(fmaxf(1.0f - num, NLL_EPS), 1.0f);
            l = -__logf(xq);
        }

        // ---- loss accumulation (q==0 lanes only) ----
        if (q == 0) {
            float wv = ev ? s_w[d] : s_wcm[d];
            accL = fmaf(l * wv, swv, accL);
            accS += swv;
        }
    }

    // ---- warp reduce ----
    #pragma unroll
    for (int o = 16; o > 0; o >>= 1) {
        accL += __shfl_xor_sync(FULL, accL, o);
        accS += __shfl_xor_sync(FULL, accS, o);
    }

    __shared__ float sL[8], sS[8];
    const int wib = threadIdx.x >> 5;
    if (lane == 0) { sL[wib] = accL; sS[wib] = accS; }
    __syncthreads();
    if (threadIdx.x == 0) {
        float bl = 0.f, bs = 0.f;
        #pragma unroll
        for (int i = 0; i < 8; ++i) { bl += sL[i]; bs += sS[i]; }
        g_partL[blockIdx.x] = (double)bl;
        g_partS[blockIdx.x] = (double)bs;
    }

    // ---- last-block finalize ----
    __shared__ bool s_last;
    __threadfence();
    if (threadIdx.x == 0) {
        unsigned t = atomicAdd(&g_ticket, 1u);
        s_last = (t == gridDim.x - 1);
    }
    __syncthreads();
    if (s_last) {
        __threadfence();
        double l2 = 0.0, w2 = 0.0;
        for (int i = threadIdx.x; i < (int)gridDim.x; i += blockDim.x) {
            l2 += g_partL[i];
            w2 += g_partS[i];
        }
        #pragma unroll
        for (int o = 16; o > 0; o >>= 1) {
            l2 += __shfl_xor_sync(FULL, l2, o);
            w2 += __shfl_xor_sync(FULL, w2, o);
        }
        __shared__ double dL[8], dS[8];
        if (lane == 0) { dL[wib] = l2; dS[wib] = w2; }
        __syncthreads();
        if (threadIdx.x == 0) {
            double tl = 0.0, tw = 0.0;
            #pragma unroll
            for (int i = 0; i < 8; ++i) { tl += dL[i]; tw += dS[i]; }
            double denom = tw > (double)NLL_EPS ? tw : (double)NLL_EPS;
            out[0] = (float)(tl / denom);
            g_ticket = 0;   // reset for next graph replay
        }
    }
}

// ---------------- launch --------------------------------------------------------
extern "C" void kernel_launch(void* const* d_in, const int* in_sizes, int n_in,
                              void* d_out, int out_size)
{
    const float* preds   = (const float*)d_in[0];
    const int2*  targets = (const int2*)d_in[1];
    const float* weight  = (const float*)d_in[2];
    const float* sw      = (const float*)d_in[3];
    float* out = (float*)d_out;

    int nrows = in_sizes[0] / 32;

    nll_kernel<<<NLL_BLOCKS, NLL_THREADS>>>(preds, targets, weight, sw, out, nrows);
}